// round 3
// baseline (speedup 1.0000x reference)
#include <cuda_runtime.h>
#include <math.h>

// B=4096, N=16384, fp32. HBM-bound stencil:
//   x = nan_checker(output); g[i] = x[i]-x[(i-1)%N];
//   out = (g < mean-4*std || g > mean+4*std) ? 0 : x
//
// R3: precompute per-column bounds ONCE (16384 sqrts instead of 67M),
// main kernel is pure load/compare/store. VPT=4, streaming hints.

#define K_SIGMA 4.0f
#define VPT 4
#define TPB 256
#define MAX_N 32768

__device__ float g_lower[MAX_N];
__device__ float g_upper[MAX_N];

__device__ __forceinline__ float sanitize(float v) {
    return isfinite(v) ? v : 0.0f;
}

__device__ __forceinline__ float4 sanitize4(float4 v) {
    v.x = sanitize(v.x); v.y = sanitize(v.y);
    v.z = sanitize(v.z); v.w = sanitize(v.w);
    return v;
}

// ---- Kernel A: per-column bounds (runs once per launch, tiny) ----
__global__ void bounds_kernel(const float* __restrict__ mean_grad,
                              const float* __restrict__ var_grad,
                              int N)
{
    int i = blockIdx.x * blockDim.x + threadIdx.x;
    if (i < N) {
        float m = mean_grad[i];
        float s = K_SIGMA * sqrtf(var_grad[i]);
        g_lower[i] = m - s;
        g_upper[i] = m + s;
    }
}

// ---- Kernel B: main streaming pass ----
__device__ __forceinline__ float4 apply4(float4 xv, float prev,
                                         float4 lo, float4 hi) {
    float4 o; float g;
    g = xv.x - prev;  o.x = (g < lo.x || g > hi.x) ? 0.0f : xv.x;
    g = xv.y - xv.x;  o.y = (g < lo.y || g > hi.y) ? 0.0f : xv.y;
    g = xv.z - xv.y;  o.z = (g < lo.z || g > hi.z) ? 0.0f : xv.z;
    g = xv.w - xv.z;  o.w = (g < lo.w || g > hi.w) ? 0.0f : xv.w;
    return o;
}

__global__ __launch_bounds__(TPB)
void correction_kernel(const float* __restrict__ x,
                       float* __restrict__ out,
                       int N)
{
    const int row = blockIdx.y;
    const long long rowOff = (long long)row * N;
    const float4* xr  = reinterpret_cast<const float4*>(x + rowOff);
    float4*       or4 = reinterpret_cast<float4*>(out + rowOff);
    const float4* lo4 = reinterpret_cast<const float4*>(g_lower);
    const float4* hi4 = reinterpret_cast<const float4*>(g_upper);

    const int baseVec = blockIdx.x * (TPB * VPT);
    const unsigned lane = threadIdx.x & 31u;

    // Front-batched x loads (MLP_p1 = 4)
    int    cv[VPT];
    float4 xv[VPT];
    #pragma unroll
    for (int i = 0; i < VPT; i++) {
        cv[i] = baseVec + i * TPB + threadIdx.x;
        xv[i] = sanitize4(__ldcs(&xr[cv[i]]));
    }

    #pragma unroll
    for (int i = 0; i < VPT; i++) {
        float prev = __shfl_up_sync(0xFFFFFFFFu, xv[i].w, 1);
        if (lane == 0) {
            int pc = (cv[i] == 0) ? (N - 1) : (cv[i] * 4 - 1);
            prev = sanitize(__ldg(&x[rowOff + pc]));
        }
        float4 lo = __ldg(&lo4[cv[i]]);
        float4 hi = __ldg(&hi4[cv[i]]);
        __stcs(&or4[cv[i]], apply4(xv[i], prev, lo, hi));
    }
}

extern "C" void kernel_launch(void* const* d_in, const int* in_sizes, int n_in,
                              void* d_out, int out_size) {
    const float* x         = (const float*)d_in[0];
    const float* mean_grad = (const float*)d_in[1];
    const float* var_grad  = (const float*)d_in[2];
    float* out             = (float*)d_out;

    int N = in_sizes[1];                       // 16384
    long long total = (long long)in_sizes[0];  // B*N
    int B = (int)(total / N);

    bounds_kernel<<<(N + 255) / 256, 256>>>(mean_grad, var_grad, N);

    int n_vec_per_row = N / 4;                 // 4096
    dim3 grid(n_vec_per_row / (TPB * VPT), B); // (4, 4096)
    correction_kernel<<<grid, TPB>>>(x, out, N);
}

// round 4
// speedup vs baseline: 1.0234x; 1.0234x over previous
#include <cuda_runtime.h>
#include <math.h>

// B=4096, N=16384, fp32. HBM-bound stencil:
//   x = nan_checker(output); g[i] = x[i]-x[(i-1)%N];
//   out = (g < mean-4*std || g > mean+4*std) ? 0 : x
//
// R4: column-stripe persistent blocks. Each block owns 2048 columns,
// computes lo/hi bounds ONCE into registers, then grid-strides over rows.
// Inner loop is pure LDG.128 / compare / STG.128 — no sqrt, no stat loads.

#define K_SIGMA 4.0f
#define VPT 2          // float4 vectors per thread
#define TPB 256
#define ROWBLOCKS 111  // ~148 SMs * 6 blocks / 8 stripes -> one resident wave

__device__ __forceinline__ float sanitize(float v) {
    return isfinite(v) ? v : 0.0f;
}

__device__ __forceinline__ float4 sanitize4(float4 v) {
    v.x = sanitize(v.x); v.y = sanitize(v.y);
    v.z = sanitize(v.z); v.w = sanitize(v.w);
    return v;
}

__device__ __forceinline__ float4 apply4(float4 xv, float prev,
                                         float4 lo, float4 hi) {
    float4 o; float g;
    g = xv.x - prev;  o.x = (g < lo.x || g > hi.x) ? 0.0f : xv.x;
    g = xv.y - xv.x;  o.y = (g < lo.y || g > hi.y) ? 0.0f : xv.y;
    g = xv.z - xv.y;  o.z = (g < lo.z || g > hi.z) ? 0.0f : xv.z;
    g = xv.w - xv.z;  o.w = (g < lo.w || g > hi.w) ? 0.0f : xv.w;
    return o;
}

__global__ __launch_bounds__(TPB)
void correction_kernel(const float* __restrict__ x,
                       const float* __restrict__ mean_grad,
                       const float* __restrict__ var_grad,
                       float* __restrict__ out,
                       int N, int B)
{
    const unsigned lane = threadIdx.x & 31u;

    // This thread's fixed column vectors (stable across all rows).
    int cv[VPT];
    #pragma unroll
    for (int i = 0; i < VPT; i++)
        cv[i] = blockIdx.x * (TPB * VPT) + i * TPB + threadIdx.x;

    // Hoisted per-column bounds -> registers (computed once per block).
    const float4* mg4 = reinterpret_cast<const float4*>(mean_grad);
    const float4* vg4 = reinterpret_cast<const float4*>(var_grad);
    float4 lo[VPT], hi[VPT];
    #pragma unroll
    for (int i = 0; i < VPT; i++) {
        float4 m = __ldg(&mg4[cv[i]]);
        float4 v = __ldg(&vg4[cv[i]]);
        float4 s;
        s.x = K_SIGMA * sqrtf(v.x);
        s.y = K_SIGMA * sqrtf(v.y);
        s.z = K_SIGMA * sqrtf(v.z);
        s.w = K_SIGMA * sqrtf(v.w);
        lo[i] = make_float4(m.x - s.x, m.y - s.y, m.z - s.z, m.w - s.w);
        hi[i] = make_float4(m.x + s.x, m.y + s.y, m.z + s.z, m.w + s.w);
    }

    // Precompute scalar-prev columns for lane 0.
    int pc[VPT];
    #pragma unroll
    for (int i = 0; i < VPT; i++)
        pc[i] = (cv[i] == 0) ? (N - 1) : (cv[i] * 4 - 1);

    // Stream rows.
    for (int row = blockIdx.y; row < B; row += gridDim.y) {
        const long long rowOff = (long long)row * N;
        const float4* xr  = reinterpret_cast<const float4*>(x + rowOff);
        float4*       or4 = reinterpret_cast<float4*>(out + rowOff);

        // Front-batched loads for MLP.
        float4 xv[VPT];
        #pragma unroll
        for (int i = 0; i < VPT; i++)
            xv[i] = sanitize4(__ldcs(&xr[cv[i]]));

        #pragma unroll
        for (int i = 0; i < VPT; i++) {
            float prev = __shfl_up_sync(0xFFFFFFFFu, xv[i].w, 1);
            if (lane == 0)
                prev = sanitize(__ldg(&x[rowOff + pc[i]]));
            __stcs(&or4[cv[i]], apply4(xv[i], prev, lo[i], hi[i]));
        }
    }
}

extern "C" void kernel_launch(void* const* d_in, const int* in_sizes, int n_in,
                              void* d_out, int out_size) {
    const float* x         = (const float*)d_in[0];
    const float* mean_grad = (const float*)d_in[1];
    const float* var_grad  = (const float*)d_in[2];
    float* out             = (float*)d_out;

    int N = in_sizes[1];                       // 16384
    long long total = (long long)in_sizes[0];  // B*N
    int B = (int)(total / N);

    int nStripes = N / (TPB * VPT * 4);        // 8
    int rowBlocks = (B < ROWBLOCKS) ? B : ROWBLOCKS;
    dim3 grid(nStripes, rowBlocks);            // (8, 111) ~= one wave
    correction_kernel<<<grid, TPB>>>(x, mean_grad, var_grad, out, N, B);
}